// round 1
// baseline (speedup 1.0000x reference)
#include <cuda_runtime.h>
#include <cuda_bf16.h>
#include <cstdint>

#define PLANES 80
#define FLAT   5120      // 80 * 64
#define NMOVES 1858
#define BATCH  16384

// Persistent scratch: the move -> flat-index map, rebuilt every launch
// (kernel_launch must be deterministic and self-contained per call).
__device__ int g_idx[NMOVES];

// ---------------------------------------------------------------------------
// Kernel A: recover src index per move column from the 0/1 selection matrix.
// fc1 is [FLAT, NMOVES] row-major. Exactly one nonzero per column.
// Grid-stride over all FLAT*NMOVES elements; coalesced reads (consecutive
// threads hit consecutive m at the same f). Division only on the rare hit.
// ---------------------------------------------------------------------------
__global__ void build_idx_kernel(const float* __restrict__ fc1) {
    const long long total = (long long)FLAT * NMOVES;
    const long long stride = (long long)gridDim.x * blockDim.x;
    for (long long t = (long long)blockIdx.x * blockDim.x + threadIdx.x;
         t < total; t += stride) {
        float v = __ldg(fc1 + t);
        if (v != 0.0f) {
            int m = (int)(t % NMOVES);
            int f = (int)(t / NMOVES);
            g_idx[m] = f;
        }
    }
}

// ---------------------------------------------------------------------------
// Kernel B: out[b, m] = x[b, g_idx[m]].
// One CTA per batch row b. Stage the full 20KB row into shared memory with
// float4 streaming loads (perfectly coalesced HBM reads), then gather from
// smem (random bank access, cheap) and emit float2 stores (out row stride
// 1858*4 = 7432 B is 8B-aligned, 1858 = 2*929 so pairs tile exactly).
// ---------------------------------------------------------------------------
__global__ __launch_bounds__(256)
void policy_gather_kernel(const float* __restrict__ x,
                          float* __restrict__ out) {
    __shared__ float row[FLAT];   // 20 KB

    const int b = blockIdx.x;
    const float4* src = reinterpret_cast<const float4*>(x + (size_t)b * FLAT);
    float4* dst = reinterpret_cast<float4*>(row);

    #pragma unroll
    for (int i = threadIdx.x; i < FLAT / 4; i += 256) {
        dst[i] = __ldg(src + i);
    }
    __syncthreads();

    float2* o = reinterpret_cast<float2*>(out + (size_t)b * NMOVES);
    // 929 float2 pairs cover 1858 outputs
    for (int p = threadIdx.x; p < NMOVES / 2; p += 256) {
        int m = 2 * p;
        float2 v;
        v.x = row[g_idx[m]];
        v.y = row[g_idx[m + 1]];
        o[p] = v;
    }
}

extern "C" void kernel_launch(void* const* d_in, const int* in_sizes, int n_in,
                              void* d_out, int out_size) {
    const float* x   = (const float*)d_in[0];   // [16384, 80, 8, 8] fp32
    const float* fc1 = (const float*)d_in[1];   // [5120, 1858] fp32
    float* out = (float*)d_out;                 // [16384, 1858] fp32

    // A: rebuild the selection index (38 MB coalesced scan)
    build_idx_kernel<<<1184, 256>>>(fc1);   // ~8 blocks/SM worth of grid

    // B: the gather
    policy_gather_kernel<<<BATCH, 256>>>(x, out);
}

// round 2
// speedup vs baseline: 1.0090x; 1.0090x over previous
#include <cuda_runtime.h>
#include <cuda_bf16.h>
#include <cstdint>

#define PLANES 80
#define FLAT   5120      // 80 * 64
#define NMOVES 1858
#define BATCH  16384

// Persistent scratch: the move -> flat-index map, rebuilt every launch
// (kernel_launch must be deterministic and self-contained per call).
__device__ int g_idx[NMOVES];

// ---------------------------------------------------------------------------
// Kernel A: recover src index per move column from the 0/1 selection matrix.
// fc1 is [FLAT, NMOVES] row-major, exactly one nonzero per column.
// float4 loads, 4 independent loads in flight per thread per iteration
// (64 B / thread / iter). Total elements 5120*1858 = 9,512,960 divisible by 4.
// ---------------------------------------------------------------------------
__global__ __launch_bounds__(256)
void build_idx_kernel(const float4* __restrict__ fc1v) {
    const long long total4 = (long long)FLAT * NMOVES / 4;   // 2,378,240
    const long long stride = (long long)gridDim.x * blockDim.x * 4;
    long long t = ((long long)blockIdx.x * blockDim.x + threadIdx.x) * 4;

    for (; t + 3 < total4; t += stride) {
        float4 v0 = __ldcs(fc1v + t + 0);
        float4 v1 = __ldcs(fc1v + t + 1);
        float4 v2 = __ldcs(fc1v + t + 2);
        float4 v3 = __ldcs(fc1v + t + 3);

        #pragma unroll
        for (int k = 0; k < 4; k++) {
            float4 v = (k == 0) ? v0 : (k == 1) ? v1 : (k == 2) ? v2 : v3;
            // rare path: at most 1858 hits across the whole 9.5M-element scan
            if (v.x != 0.0f || v.y != 0.0f || v.z != 0.0f || v.w != 0.0f) {
                long long e = (t + k) * 4;
                const float* p = reinterpret_cast<const float*>(&v);
                #pragma unroll
                for (int j = 0; j < 4; j++) {
                    if (p[j] != 0.0f) {
                        long long ej = e + j;
                        int m = (int)(ej % NMOVES);
                        int f = (int)(ej / NMOVES);
                        g_idx[m] = f;
                    }
                }
            }
        }
    }
    // tail (total4 is divisible by 4 for these shapes, but keep it safe)
    for (; t < total4; t++) {
        float4 v = __ldcs(fc1v + t);
        const float* p = reinterpret_cast<const float*>(&v);
        #pragma unroll
        for (int j = 0; j < 4; j++) {
            if (p[j] != 0.0f) {
                long long ej = t * 4 + j;
                g_idx[(int)(ej % NMOVES)] = (int)(ej / NMOVES);
            }
        }
    }
}

// ---------------------------------------------------------------------------
// Kernel B: out[b, m] = x[b, g_idx[m]].
// One CTA per batch row b. Stage the full 20KB row into shared memory with
// float4 streaming loads (coalesced, evict-first), gather from smem, emit
// float2 streaming stores (out rows are 8B-aligned; 1858 = 2*929).
// ---------------------------------------------------------------------------
__global__ __launch_bounds__(256)
void policy_gather_kernel(const float* __restrict__ x,
                          float* __restrict__ out) {
    __shared__ float row[FLAT];   // 20 KB

    const int b = blockIdx.x;
    const float4* src = reinterpret_cast<const float4*>(x + (size_t)b * FLAT);
    float4* dst = reinterpret_cast<float4*>(row);

    #pragma unroll
    for (int i = threadIdx.x; i < FLAT / 4; i += 256) {
        dst[i] = __ldcs(src + i);
    }
    __syncthreads();

    float2* o = reinterpret_cast<float2*>(out + (size_t)b * NMOVES);
    // 929 float2 pairs cover 1858 outputs
    for (int p = threadIdx.x; p < NMOVES / 2; p += 256) {
        int m = 2 * p;
        float2 v;
        v.x = row[g_idx[m]];
        v.y = row[g_idx[m + 1]];
        __stcs(o + p, v);
    }
}

extern "C" void kernel_launch(void* const* d_in, const int* in_sizes, int n_in,
                              void* d_out, int out_size) {
    const float* x   = (const float*)d_in[0];   // [16384, 80, 8, 8] fp32
    const float* fc1 = (const float*)d_in[1];   // [5120, 1858] fp32
    float* out = (float*)d_out;                 // [16384, 1858] fp32

    // A: rebuild the selection index (38 MB vectorized scan, ~6 us)
    // 2,378,240 float4 / (256 thr * 4 per thr) = 2323 blocks -> one pass
    build_idx_kernel<<<2323, 256>>>(reinterpret_cast<const float4*>(fc1));

    // B: the gather (HBM-roofline bound)
    policy_gather_kernel<<<BATCH, 256>>>(x, out);
}

// round 3
// speedup vs baseline: 1.0848x; 1.0751x over previous
#include <cuda_runtime.h>
#include <cuda_bf16.h>
#include <cstdint>

#define PLANES 80
#define FLAT   5120      // 80 * 64
#define NMOVES 1858
#define BATCH  16384
#define ROW_BYTES (FLAT * 4)   // 20480

// move -> flat-index map, rebuilt every launch (deterministic per call).
// 8-byte aligned so pairs can be read as int2.
__device__ __align__(16) int g_idx[NMOVES];

// ---------------------------------------------------------------------------
// small PTX helpers
// ---------------------------------------------------------------------------
__device__ __forceinline__ uint32_t smem_u32(const void* p) {
    uint32_t a;
    asm("{ .reg .u64 t; cvta.to.shared.u64 t, %1; cvt.u32.u64 %0, t; }"
        : "=r"(a) : "l"(p));
    return a;
}

__device__ __forceinline__ void mbar_init(uint32_t addr, uint32_t count) {
    asm volatile("mbarrier.init.shared.b64 [%0], %1;" :: "r"(addr), "r"(count) : "memory");
}

__device__ __forceinline__ void mbar_expect_tx(uint32_t addr, uint32_t bytes) {
    asm volatile("mbarrier.arrive.expect_tx.shared.b64 _, [%0], %1;"
                 :: "r"(addr), "r"(bytes) : "memory");
}

__device__ __forceinline__ void bulk_g2s(uint32_t dst_smem, const void* gsrc,
                                         uint32_t bytes, uint32_t mbar) {
    asm volatile(
        "cp.async.bulk.shared::cta.global.mbarrier::complete_tx::bytes "
        "[%0], [%1], %2, [%3];"
        :: "r"(dst_smem), "l"(gsrc), "r"(bytes), "r"(mbar) : "memory");
}

__device__ __forceinline__ void mbar_wait(uint32_t addr, uint32_t phase) {
    asm volatile(
        "{\n\t"
        ".reg .pred P;\n\t"
        "W%=:\n\t"
        "mbarrier.try_wait.parity.acquire.cta.shared::cta.b64 P, [%0], %1, 0x989680;\n\t"
        "@!P bra W%=;\n\t"
        "}"
        :: "r"(addr), "r"(phase) : "memory");
}

// ---------------------------------------------------------------------------
// Kernel A: recover src index per move column from the 0/1 selection matrix.
// Lane-interleaved float4 loads: each LDG.128 is a fully coalesced 512B warp
// access; 8 independent loads per thread (MLP=8). 38 MB scan.
// ---------------------------------------------------------------------------
__global__ __launch_bounds__(256)
void build_idx_kernel(const uint4* __restrict__ fc1v) {
    const long long total4 = (long long)FLAT * NMOVES / 4;   // 2,378,240
    const int warp = (blockIdx.x * 256 + threadIdx.x) >> 5;
    const int lane = threadIdx.x & 31;
    const long long base = (long long)warp * 256 + lane;     // float4 index

    #pragma unroll
    for (int j = 0; j < 8; j++) {
        long long t = base + (long long)j * 32;
        if (t < total4) {
            uint4 v = __ldcs(fc1v + t);
            if (v.x | v.y | v.z | v.w) {     // rare: <=1858 hits in 9.5M elems
                long long e = t * 4;
                unsigned u0 = v.x, u1 = v.y, u2 = v.z, u3 = v.w;
                if (u0) { long long ek = e + 0; g_idx[(int)(ek % NMOVES)] = (int)(ek / NMOVES); }
                if (u1) { long long ek = e + 1; g_idx[(int)(ek % NMOVES)] = (int)(ek / NMOVES); }
                if (u2) { long long ek = e + 2; g_idx[(int)(ek % NMOVES)] = (int)(ek / NMOVES); }
                if (u3) { long long ek = e + 3; g_idx[(int)(ek % NMOVES)] = (int)(ek / NMOVES); }
            }
        }
    }
}

// ---------------------------------------------------------------------------
// Kernel B: out[b, m] = x[b, g_idx[m]].
// One CTA per batch row. Stage the 20KB row via 1D bulk-async copy (TMA path),
// preload gather indices into registers while the copy is in flight, then
// gather from smem and emit float2 streaming stores.
// 929 float2 pairs per row: thread t handles pairs t, t+256, t+512, (t+768).
// ---------------------------------------------------------------------------
__global__ __launch_bounds__(256)
void policy_gather_kernel(const float* __restrict__ x,
                          float* __restrict__ out) {
    __shared__ __align__(128) float row[FLAT];           // 20 KB
    __shared__ __align__(8) unsigned long long mbar;

    const int tid = threadIdx.x;
    const int b = blockIdx.x;
    const uint32_t mbar_a = smem_u32(&mbar);
    const uint32_t row_a  = smem_u32(row);

    if (tid == 0) mbar_init(mbar_a, 1);
    __syncthreads();
    if (tid == 0) {
        mbar_expect_tx(mbar_a, ROW_BYTES);
        bulk_g2s(row_a, x + (size_t)b * FLAT, ROW_BYTES, mbar_a);
    }

    // Preload gather indices while the bulk copy is in flight.
    const int2* idxp = reinterpret_cast<const int2*>(g_idx);
    const int2 i0 = idxp[tid];
    const int2 i1 = idxp[tid + 256];
    const int2 i2 = idxp[tid + 512];
    const bool has3 = tid < (NMOVES / 2 - 768);          // 161 threads
    int2 i3 = make_int2(0, 0);
    if (has3) i3 = idxp[tid + 768];

    mbar_wait(mbar_a, 0);

    float2* o = reinterpret_cast<float2*>(out + (size_t)b * NMOVES);
    float2 v;
    v.x = row[i0.x]; v.y = row[i0.y]; __stcs(o + tid,       v);
    v.x = row[i1.x]; v.y = row[i1.y]; __stcs(o + tid + 256, v);
    v.x = row[i2.x]; v.y = row[i2.y]; __stcs(o + tid + 512, v);
    if (has3) {
        v.x = row[i3.x]; v.y = row[i3.y]; __stcs(o + tid + 768, v);
    }
}

extern "C" void kernel_launch(void* const* d_in, const int* in_sizes, int n_in,
                              void* d_out, int out_size) {
    const float* x   = (const float*)d_in[0];   // [16384, 80, 8, 8] fp32
    const float* fc1 = (const float*)d_in[1];   // [5120, 1858] fp32
    float* out = (float*)d_out;                 // [16384, 1858] fp32

    // A: rebuild the selection index.
    // warps needed = ceil(2,378,240 / 256) = 9290 -> 1162 blocks of 8 warps.
    build_idx_kernel<<<1162, 256>>>(reinterpret_cast<const uint4*>(fc1));

    // B: the gather (HBM-roofline bound)
    policy_gather_kernel<<<BATCH, 256>>>(x, out);
}